// round 1
// baseline (speedup 1.0000x reference)
#include <cuda_runtime.h>

#define NSP  13824      // 24^3
#define NPAD 17576      // 26^3
#define CCH  64
#define BB   2
#define NBLK_GATE 432   // 13824/32

// scratch (zero-initialized at module load; padded borders of g_xk/g_xv stay 0 forever)
__device__ float g_xq[BB*CCH*NSP];
__device__ float g_xk[BB*CCH*NPAD];
__device__ float g_xv[BB*CCH*NPAD];
__device__ float g_attn[BB*CCH*NSP];
__device__ float g_part[BB*NBLK_GATE*CCH];

__device__ __forceinline__ float ex2f_(float x){ float y; asm("ex2.approx.ftz.f32 %0, %1;":"=f"(y):"f"(x)); return y; }
__device__ __forceinline__ float rcpf_(float x){ float y; asm("rcp.approx.ftz.f32 %0, %1;":"=f"(y):"f"(x)); return y; }
__device__ __forceinline__ float sigmf_(float x){ return rcpf_(1.f + ex2f_(-1.44269504f*x)); }

// ---------------- Phase A: q/k/v channel-mix projections ----------------
// q -> unpadded, pre-scaled by log2e/8 (bias included)
// k,v -> zero-bordered padded layout (bias NOT included; added in attention)
__global__ __launch_bounds__(256) void proj_kernel(
    const float* __restrict__ x, const float* __restrict__ Wq, const float* __restrict__ bq,
    const float* __restrict__ Wk, const float* __restrict__ Wv)
{
    __shared__ float xs[64][64];
    __shared__ float Ws[64][65];
    __shared__ float bias[64];
    int b = blockIdx.y, n0 = blockIdx.x*64, tid = threadIdx.x;
    for (int i=tid;i<4096;i+=256){int c=i>>6,nl=i&63; xs[c][nl] = x[(b*64+c)*NSP + n0+nl];}
    if (tid<64) bias[tid]=bq[tid];
    int obase=(tid>>4)<<2, nb=(tid&15)<<2;
    int nidx[4], npv[4];
    #pragma unroll
    for (int j=0;j<4;j++){
        int n=n0+nb+j; nidx[j]=n;
        int h=n/576, r=n-h*576, d=r/24, w=r-d*24;
        npv[j]=(h+1)*676+(d+1)*26+(w+1);
    }
    for (int pass=0; pass<3; pass++){
        const float* W = pass==0?Wq:(pass==1?Wk:Wv);
        __syncthreads();
        for (int i=tid;i<4096;i+=256) Ws[i>>6][i&63]=W[i];
        __syncthreads();
        float acc[4][4];
        #pragma unroll
        for (int i=0;i<4;i++){
            float bi = (pass==0)? bias[obase+i] : 0.f;
            #pragma unroll
            for (int j=0;j<4;j++) acc[i][j]=bi;
        }
        #pragma unroll 4
        for (int c=0;c<64;c++){
            float4 xr = *(const float4*)&xs[c][nb];
            #pragma unroll
            for (int i=0;i<4;i++){
                float wv = Ws[obase+i][c];
                acc[i][0]=fmaf(wv,xr.x,acc[i][0]);
                acc[i][1]=fmaf(wv,xr.y,acc[i][1]);
                acc[i][2]=fmaf(wv,xr.z,acc[i][2]);
                acc[i][3]=fmaf(wv,xr.w,acc[i][3]);
            }
        }
        if (pass==0){
            #pragma unroll
            for (int i=0;i<4;i++)
                #pragma unroll
                for (int j=0;j<4;j++)
                    g_xq[(b*64+obase+i)*NSP + nidx[j]] = acc[i][j]*0.18033688011112042f; // (1/8)*log2(e)
        } else {
            float* dst = (pass==1)? g_xk : g_xv;
            #pragma unroll
            for (int i=0;i<4;i++)
                #pragma unroll
                for (int j=0;j<4;j++)
                    dst[(b*64+obase+i)*NPAD + npv[j]] = acc[i][j];
        }
    }
}

// ---------------- Phase B: per-channel scalar softmax attention ----------------
__global__ __launch_bounds__(256) void attn_kernel(
    const float* __restrict__ bk, const float* __restrict__ bv,
    const float* __restrict__ mk, const float* __restrict__ mv)
{
    int bc = blockIdx.y;              // b*64 + c
    int c  = bc & 63;
    int n  = blockIdx.x*256 + threadIdx.x;
    int h=n/576, r=n-h*576, d=r/24, w=r-d*24;
    int np=(h+1)*676+(d+1)*26+(w+1);
    float qs  = g_xq[bc*NSP+n];       // q * log2e/8
    float bkc = __ldg(bk+c), bvc = __ldg(bv+c);
    float qbk = qs*bkc;
    const float* Kp = g_xk + bc*NPAD + np;
    const float* Vp = g_xv + bc*NPAD + np;
    float den=0.f, num=0.f, dens=0.f;
    #pragma unroll
    for (int m=0;m<5;m++){
        float e = ex2f_(qs*__ldg(mk+c*5+m));
        den += e;
        num  = fmaf(e, __ldg(mv+c*5+m), num);
    }
    #pragma unroll
    for (int j=0;j<27;j++){
        int dz=j/9, rr=j-dz*9, dy=rr/3, dx=rr-dy*3;
        int off=(dz-1)*676+(dy-1)*26+(dx-1);
        float kv=__ldg(Kp+off), vv=__ldg(Vp+off);
        float e = ex2f_(fmaf(qs,kv,qbk)); // exp((q*(xk+bk))/8)
        dens += e;
        num   = fmaf(e,vv,num);
    }
    num = fmaf(bvc,dens,num);             // spatial v = xv + bv
    g_attn[bc*NSP+n] = num * rcpf_(den+dens);
}

// ---------------- Phase C: gate + blend + per-block channel sums ----------------
__global__ __launch_bounds__(256) void gate_kernel(
    const float* __restrict__ x, const float* __restrict__ Wg,
    const float* __restrict__ bg, float* __restrict__ out)
{
    __shared__ float xs[64][33];
    __shared__ float as[64][33];
    __shared__ float Wb[64][65];
    __shared__ float ssum[64];
    int b=blockIdx.y, n0=blockIdx.x*32, tid=threadIdx.x;
    if (tid<64) ssum[tid]=0.f;
    for (int i=tid;i<2048;i+=256){
        int cc=i>>5, nl=i&31;
        xs[cc][nl]=x[(b*64+cc)*NSP+n0+nl];
        as[cc][nl]=g_attn[(b*64+cc)*NSP+n0+nl];
    }
    int obase=(tid>>4)<<2, nb=(tid&15)<<1;
    float acc[4][2]={};
    for (int half=0;half<2;half++){
        __syncthreads();
        for (int i=tid;i<4096;i+=256) Wb[i>>6][i&63]=Wg[(i>>6)*128 + half*64 + (i&63)];
        __syncthreads();
        #pragma unroll 4
        for (int cc=0;cc<64;cc++){
            float s0 = half ? as[cc][nb]   : xs[cc][nb];
            float s1 = half ? as[cc][nb+1] : xs[cc][nb+1];
            #pragma unroll
            for (int i=0;i<4;i++){
                float wv=Wb[obase+i][cc];
                acc[i][0]=fmaf(wv,s0,acc[i][0]);
                acc[i][1]=fmaf(wv,s1,acc[i][1]);
            }
        }
    }
    #pragma unroll
    for (int i=0;i<4;i++){
        int o=obase+i;
        float bgo=__ldg(bg+o);
        float lsum=0.f;
        #pragma unroll
        for (int j=0;j<2;j++){
            float g  = sigmf_(acc[i][j]+bgo);
            float ov = g*as[o][nb+j] + (1.f-g)*xs[o][nb+j];
            out[(b*64+o)*NSP + n0+nb+j] = ov;
            lsum += ov;
        }
        atomicAdd(&ssum[o], lsum);
    }
    __syncthreads();
    if (tid<64) g_part[(b*NBLK_GATE+blockIdx.x)*64 + tid] = ssum[tid];
}

// ---------------- Phase D: pooled-mean + GRU memory update ----------------
__global__ __launch_bounds__(128) void gru_kernel(
    const float* __restrict__ prev, const float* __restrict__ Wih, const float* __restrict__ Whh,
    const float* __restrict__ bih, const float* __restrict__ bhh, float* __restrict__ out_mem)
{
    __shared__ float mu[2][64], pm[2][64];
    int tid=threadIdx.x;
    int b=tid>>6, o=tid&63;
    {
        float s=0.f;
        for (int k2=0;k2<NBLK_GATE;k2++) s += g_part[(b*NBLK_GATE+k2)*64 + o];
        mu[b][o] = s * (1.f/13824.f);
        pm[b][o] = prev[tid];
    }
    __syncthreads();
    float gir=bih[o], giz=bih[64+o], gin=bih[128+o];
    float ghr=bhh[o], ghz=bhh[64+o], ghn=bhh[128+o];
    for (int cc=0;cc<64;cc++){
        float m=mu[b][cc], p=pm[b][cc];
        gir = fmaf(Wih[o*64+cc],        m, gir);
        giz = fmaf(Wih[(64+o)*64+cc],   m, giz);
        gin = fmaf(Wih[(128+o)*64+cc],  m, gin);
        ghr = fmaf(Whh[o*64+cc],        p, ghr);
        ghz = fmaf(Whh[(64+o)*64+cc],   p, ghz);
        ghn = fmaf(Whh[(128+o)*64+cc],  p, ghn);
    }
    float rg = 1.f/(1.f+expf(-(gir+ghr)));
    float zg = 1.f/(1.f+expf(-(giz+ghz)));
    float ng2 = tanhf(gin + rg*ghn);
    out_mem[tid] = (1.f-zg)*ng2 + zg*pm[b][o];
}

extern "C" void kernel_launch(void* const* d_in, const int* in_sizes, int n_in,
                              void* d_out, int out_size)
{
    const float* x   = (const float*)d_in[0];
    const float* prev= (const float*)d_in[1];
    const float* Wq  = (const float*)d_in[2];
    const float* bq  = (const float*)d_in[3];
    const float* Wk  = (const float*)d_in[4];
    const float* bk  = (const float*)d_in[5];
    const float* Wv  = (const float*)d_in[6];
    const float* bv  = (const float*)d_in[7];
    const float* mk  = (const float*)d_in[8];
    const float* mv  = (const float*)d_in[9];
    const float* Wg  = (const float*)d_in[10];
    const float* bg  = (const float*)d_in[11];
    const float* Wih = (const float*)d_in[12];
    const float* Whh = (const float*)d_in[13];
    const float* bih = (const float*)d_in[14];
    const float* bhh = (const float*)d_in[15];
    float* out = (float*)d_out;

    proj_kernel<<<dim3(216,2),256>>>(x,Wq,bq,Wk,Wv);
    attn_kernel<<<dim3(54,128),256>>>(bk,bv,mk,mv);
    gate_kernel<<<dim3(NBLK_GATE,2),256>>>(x,Wg,bg,out);
    if (out_size >= BB*CCH*NSP + BB*CCH)
        gru_kernel<<<1,128>>>(prev,Wih,Whh,bih,bhh,out + (size_t)BB*CCH*NSP);
}

// round 2
// speedup vs baseline: 1.2790x; 1.2790x over previous
#include <cuda_runtime.h>

#define NSP  13824      // 24^3
#define NPAD 17576      // 26^3
#define CCH  64
#define BB   2
#define NBLK_GATE 432   // 13824/32

// scratch (zero-initialized at module load; padded borders of g_xk/g_xv stay 0 forever)
__device__ float g_xq[BB*CCH*NSP];
__device__ float g_xk[BB*CCH*NPAD];
__device__ float g_xv[BB*CCH*NPAD];
__device__ float g_attn[BB*CCH*NSP];
__device__ float g_part[BB*CCH*NBLK_GATE];   // [ (b*64+o)*432 + blk ]  (transposed for coalesced reduce)

__device__ __forceinline__ float ex2f_(float x){ float y; asm("ex2.approx.ftz.f32 %0, %1;":"=f"(y):"f"(x)); return y; }
__device__ __forceinline__ float rcpf_(float x){ float y; asm("rcp.approx.ftz.f32 %0, %1;":"=f"(y):"f"(x)); return y; }
__device__ __forceinline__ float sigmf_(float x){ return rcpf_(1.f + ex2f_(-1.44269504f*x)); }

// ---------------- Phase A: q/k/v channel-mix projections ----------------
__global__ __launch_bounds__(256) void proj_kernel(
    const float* __restrict__ x, const float* __restrict__ Wq, const float* __restrict__ bq,
    const float* __restrict__ Wk, const float* __restrict__ Wv)
{
    __shared__ float xs[64][64];
    __shared__ float Ws[64][65];
    __shared__ float bias[64];
    int b = blockIdx.y, n0 = blockIdx.x*64, tid = threadIdx.x;
    for (int i=tid;i<4096;i+=256){int c=i>>6,nl=i&63; xs[c][nl] = x[(b*64+c)*NSP + n0+nl];}
    if (tid<64) bias[tid]=bq[tid];
    int obase=(tid>>4)<<2, nb=(tid&15)<<2;
    int nidx[4], npv[4];
    #pragma unroll
    for (int j=0;j<4;j++){
        int n=n0+nb+j; nidx[j]=n;
        int h=n/576, r=n-h*576, d=r/24, w=r-d*24;
        npv[j]=(h+1)*676+(d+1)*26+(w+1);
    }
    for (int pass=0; pass<3; pass++){
        const float* W = pass==0?Wq:(pass==1?Wk:Wv);
        __syncthreads();
        for (int i=tid;i<4096;i+=256) Ws[i>>6][i&63]=W[i];
        __syncthreads();
        float acc[4][4];
        #pragma unroll
        for (int i=0;i<4;i++){
            float bi = (pass==0)? bias[obase+i] : 0.f;
            #pragma unroll
            for (int j=0;j<4;j++) acc[i][j]=bi;
        }
        #pragma unroll 4
        for (int c=0;c<64;c++){
            float4 xr = *(const float4*)&xs[c][nb];
            #pragma unroll
            for (int i=0;i<4;i++){
                float wv = Ws[obase+i][c];
                acc[i][0]=fmaf(wv,xr.x,acc[i][0]);
                acc[i][1]=fmaf(wv,xr.y,acc[i][1]);
                acc[i][2]=fmaf(wv,xr.z,acc[i][2]);
                acc[i][3]=fmaf(wv,xr.w,acc[i][3]);
            }
        }
        if (pass==0){
            #pragma unroll
            for (int i=0;i<4;i++)
                #pragma unroll
                for (int j=0;j<4;j++)
                    g_xq[(b*64+obase+i)*NSP + nidx[j]] = acc[i][j]*0.18033688011112042f; // (1/8)*log2(e)
        } else {
            float* dst = (pass==1)? g_xk : g_xv;
            #pragma unroll
            for (int i=0;i<4;i++)
                #pragma unroll
                for (int j=0;j<4;j++)
                    dst[(b*64+obase+i)*NPAD + npv[j]] = acc[i][j];
        }
    }
}

// ---------------- Phase B: per-channel scalar softmax attention ----------------
__global__ __launch_bounds__(256) void attn_kernel(
    const float* __restrict__ bk, const float* __restrict__ bv,
    const float* __restrict__ mk, const float* __restrict__ mv)
{
    int bc = blockIdx.y;              // b*64 + c
    int c  = bc & 63;
    int n  = blockIdx.x*256 + threadIdx.x;
    int h=n/576, r=n-h*576, d=r/24, w=r-d*24;
    int np=(h+1)*676+(d+1)*26+(w+1);
    float qs  = g_xq[bc*NSP+n];       // q * log2e/8
    float bkc = __ldg(bk+c), bvc = __ldg(bv+c);
    float qbk = qs*bkc;
    const float* Kp = g_xk + bc*NPAD + np;
    const float* Vp = g_xv + bc*NPAD + np;
    float den=0.f, num=0.f, dens=0.f;
    #pragma unroll
    for (int m=0;m<5;m++){
        float e = ex2f_(qs*__ldg(mk+c*5+m));
        den += e;
        num  = fmaf(e, __ldg(mv+c*5+m), num);
    }
    #pragma unroll
    for (int j=0;j<27;j++){
        int dz=j/9, rr=j-dz*9, dy=rr/3, dx=rr-dy*3;
        int off=(dz-1)*676+(dy-1)*26+(dx-1);
        float kv=__ldg(Kp+off), vv=__ldg(Vp+off);
        float e = ex2f_(fmaf(qs,kv,qbk)); // exp((q*(xk+bk))/8)
        dens += e;
        num   = fmaf(e,vv,num);
    }
    num = fmaf(bvc,dens,num);             // spatial v = xv + bv
    g_attn[bc*NSP+n] = num * rcpf_(den+dens);
}

// ---------------- Phase C: gate + blend + per-block channel sums ----------------
__global__ __launch_bounds__(256) void gate_kernel(
    const float* __restrict__ x, const float* __restrict__ Wg,
    const float* __restrict__ bg, float* __restrict__ out)
{
    __shared__ float xs[64][33];
    __shared__ float as[64][33];
    __shared__ float Wb[64][65];
    __shared__ float ssum[64];
    int b=blockIdx.y, n0=blockIdx.x*32, tid=threadIdx.x;
    if (tid<64) ssum[tid]=0.f;
    for (int i=tid;i<2048;i+=256){
        int cc=i>>5, nl=i&31;
        xs[cc][nl]=x[(b*64+cc)*NSP+n0+nl];
        as[cc][nl]=g_attn[(b*64+cc)*NSP+n0+nl];
    }
    int obase=(tid>>4)<<2, nb=(tid&15)<<1;
    float acc[4][2]={};
    for (int half=0;half<2;half++){
        __syncthreads();
        for (int i=tid;i<4096;i+=256) Wb[i>>6][i&63]=Wg[(i>>6)*128 + half*64 + (i&63)];
        __syncthreads();
        #pragma unroll 4
        for (int cc=0;cc<64;cc++){
            float s0 = half ? as[cc][nb]   : xs[cc][nb];
            float s1 = half ? as[cc][nb+1] : xs[cc][nb+1];
            #pragma unroll
            for (int i=0;i<4;i++){
                float wv=Wb[obase+i][cc];
                acc[i][0]=fmaf(wv,s0,acc[i][0]);
                acc[i][1]=fmaf(wv,s1,acc[i][1]);
            }
        }
    }
    #pragma unroll
    for (int i=0;i<4;i++){
        int o=obase+i;
        float bgo=__ldg(bg+o);
        float lsum=0.f;
        #pragma unroll
        for (int j=0;j<2;j++){
            float g  = sigmf_(acc[i][j]+bgo);
            float ov = g*as[o][nb+j] + (1.f-g)*xs[o][nb+j];
            out[(b*64+o)*NSP + n0+nb+j] = ov;
            lsum += ov;
        }
        atomicAdd(&ssum[o], lsum);
    }
    __syncthreads();
    if (tid<64) g_part[(b*64+tid)*NBLK_GATE + blockIdx.x] = ssum[tid];  // transposed layout
}

// ---------------- Phase D: pooled-mean + GRU memory update (1024 thr, coalesced) ----------------
__global__ __launch_bounds__(1024) void gru_kernel(
    const float* __restrict__ prev, const float* __restrict__ Wih, const float* __restrict__ Whh,
    const float* __restrict__ bih, const float* __restrict__ bhh, float* __restrict__ out_mem)
{
    __shared__ float red[1024];
    __shared__ float mu[128], pm[128];
    int tid = threadIdx.x;

    // Phase 1: 8 threads per (b,o) pair, contiguous-ish strided reads (coalesced in groups of 8)
    {
        int p = tid >> 3, s = tid & 7;
        const float* base = g_part + p*NBLK_GATE;
        float acc = 0.f;
        #pragma unroll 6
        for (int i = s; i < NBLK_GATE; i += 8) acc += base[i];
        red[tid] = acc;
    }
    if (tid < 128) pm[tid] = prev[tid];
    __syncthreads();
    if ((tid & 7) == 0){
        int p = tid >> 3;
        float t = 0.f;
        #pragma unroll
        for (int k2 = 0; k2 < 8; k2++) t += red[p*8 + k2];
        mu[p] = t * (1.f/13824.f);
    }
    __syncthreads();

    // Phase 2: warp per (b,o) pair; lane index = input channel -> coalesced weight loads
    int w = tid >> 5, lane = tid & 31;
    #pragma unroll
    for (int rep = 0; rep < 4; rep++){
        int p2 = w + rep*32;          // 0..127
        int b = p2 >> 6, o = p2 & 63;
        float a0=0.f,a1=0.f,a2=0.f,a3=0.f,a4=0.f,a5=0.f;
        #pragma unroll
        for (int half = 0; half < 2; half++){
            int cc = lane + half*32;
            float m  = mu[b*64+cc];
            float pv = pm[b*64+cc];
            a0 = fmaf(__ldg(Wih + o*64        + cc), m,  a0);
            a1 = fmaf(__ldg(Wih + (64+o)*64   + cc), m,  a1);
            a2 = fmaf(__ldg(Wih + (128+o)*64  + cc), m,  a2);
            a3 = fmaf(__ldg(Whh + o*64        + cc), pv, a3);
            a4 = fmaf(__ldg(Whh + (64+o)*64   + cc), pv, a4);
            a5 = fmaf(__ldg(Whh + (128+o)*64  + cc), pv, a5);
        }
        #pragma unroll
        for (int off = 16; off; off >>= 1){
            a0 += __shfl_xor_sync(0xffffffffu, a0, off);
            a1 += __shfl_xor_sync(0xffffffffu, a1, off);
            a2 += __shfl_xor_sync(0xffffffffu, a2, off);
            a3 += __shfl_xor_sync(0xffffffffu, a3, off);
            a4 += __shfl_xor_sync(0xffffffffu, a4, off);
            a5 += __shfl_xor_sync(0xffffffffu, a5, off);
        }
        if (lane == 0){
            float gir = a0 + bih[o],     ghr = a3 + bhh[o];
            float giz = a1 + bih[64+o],  ghz = a4 + bhh[64+o];
            float gin = a2 + bih[128+o], ghn = a5 + bhh[128+o];
            float rg  = 1.f/(1.f+expf(-(gir+ghr)));
            float zg  = 1.f/(1.f+expf(-(giz+ghz)));
            float ng2 = tanhf(gin + rg*ghn);
            out_mem[p2] = (1.f-zg)*ng2 + zg*pm[b*64+o];
        }
    }
}

extern "C" void kernel_launch(void* const* d_in, const int* in_sizes, int n_in,
                              void* d_out, int out_size)
{
    const float* x   = (const float*)d_in[0];
    const float* prev= (const float*)d_in[1];
    const float* Wq  = (const float*)d_in[2];
    const float* bq  = (const float*)d_in[3];
    const float* Wk  = (const float*)d_in[4];
    const float* bk  = (const float*)d_in[5];
    const float* Wv  = (const float*)d_in[6];
    const float* bv  = (const float*)d_in[7];
    const float* mk  = (const float*)d_in[8];
    const float* mv  = (const float*)d_in[9];
    const float* Wg  = (const float*)d_in[10];
    const float* bg  = (const float*)d_in[11];
    const float* Wih = (const float*)d_in[12];
    const float* Whh = (const float*)d_in[13];
    const float* bih = (const float*)d_in[14];
    const float* bhh = (const float*)d_in[15];
    float* out = (float*)d_out;

    proj_kernel<<<dim3(216,2),256>>>(x,Wq,bq,Wk,Wv);
    attn_kernel<<<dim3(54,128),256>>>(bk,bv,mk,mv);
    gate_kernel<<<dim3(NBLK_GATE,2),256>>>(x,Wg,bg,out);
    if (out_size >= BB*CCH*NSP + BB*CCH)
        gru_kernel<<<1,1024>>>(prev,Wih,Whh,bih,bhh,out + (size_t)BB*CCH*NSP);
}